// round 5
// baseline (speedup 1.0000x reference)
#include <cuda_runtime.h>

typedef unsigned long long ull;

// ---------------- packed f32x2 helpers (Blackwell FFMA2 path) ----------------
__device__ __forceinline__ ull pack2(float a, float b) {
    ull r; asm("mov.b64 %0, {%1,%2};" : "=l"(r) : "f"(a), "f"(b)); return r;
}
__device__ __forceinline__ float2 unpack2(ull v) {
    float2 f; asm("mov.b64 {%0,%1}, %2;" : "=f"(f.x), "=f"(f.y) : "l"(v)); return f;
}
__device__ __forceinline__ ull ffma2(ull a, ull b, ull c) {
    ull d; asm("fma.rn.f32x2 %0, %1, %2, %3;" : "=l"(d) : "l"(a), "l"(b), "l"(c)); return d;
}
__device__ __forceinline__ ull fadd2(ull a, ull b) {
    ull d; asm("add.rn.f32x2 %0, %1, %2;" : "=l"(d) : "l"(a), "l"(b)); return d;
}

// HW tanh (single MUFU op); validated rel_err ~7e-7 end-to-end
__device__ __forceinline__ float tanh_fast(float x) {
    float y; asm("tanh.approx.f32 %0, %1;" : "=f"(y) : "f"(x)); return y;
}
__device__ __forceinline__ float sig_fast(float x) {
    return fmaf(0.5f, tanh_fast(0.5f * x), 0.5f);
}
__device__ __forceinline__ float sigmoidf_acc(float x) {
    return __fdividef(1.f, 1.f + __expf(-x));
}

#define B_  256
#define S_  1024
#define F_  64
#define H_  64
#define G_  256   // 4*H

// Pair mapping: pair index p -> u = p>>1, s = p&1
//   s=0: columns (u,     u+64 ) = (z_i[u],  z_f[u])
//   s=1: columns (u+128, u+192) = (z_c[u],  z_o[u])
// xz scratch: [t][b][p] packed float2 (col c0, col c1). 268MB.
__device__ ull g_xz[(size_t)S_ * B_ * 128];

// =====================================================================
// Kernel A: xz = x @ kernel + bias
// 2048 CTAs x 128 thr, 3 CTAs/SM (12 warps) to hide LDG/bar latency.
// Each CTA: 128 consecutive global rows (n = b*S + t), 1 row per iter.
// =====================================================================
__global__ void __launch_bounds__(128, 3) lstm_xgemm(
    const float* __restrict__ x, const float* __restrict__ kern,
    const float* __restrict__ bias)
{
    const int tid = threadIdx.x;
    const int j   = tid;              // pair index 0..127
    const int u   = j >> 1;
    const int s   = j & 1;
    const int c0  = u + (s ? 128 : 0);
    const int c1  = c0 + 64;

    // weights packed along k: wX[m] = (kern[2m][c], kern[2m+1][c])
    ull wA[32], wB[32];
#pragma unroll
    for (int m = 0; m < 32; m++) {
        wA[m] = pack2(kern[(2 * m) * G_ + c0], kern[(2 * m + 1) * G_ + c0]);
        wB[m] = pack2(kern[(2 * m) * G_ + c1], kern[(2 * m + 1) * G_ + c1]);
    }
    const float bc0 = bias[c0], bc1 = bias[c1];

    __shared__ __align__(16) ull xpk[2][32];   // x packed (x_2m, x_2m+1), 2 buffers

    const int base = blockIdx.x * 128;         // 128 rows per CTA

    float2 v = make_float2(0.f, 0.f);
    if (tid < 32) v = *(const float2*)(x + (size_t)base * F_ + 2 * tid);

    int buf = 0;
    for (int i = 0; i < 128; i++) {
        if (tid < 32) xpk[buf][tid] = pack2(v.x, v.y);
        __syncthreads();
        if (tid < 32 && i + 1 < 128)
            v = *(const float2*)(x + (size_t)(base + i + 1) * F_ + 2 * tid);

        const ull* xa = xpk[buf];
        ull a0 = 0, a1 = 0, a2 = 0, a3 = 0;
#pragma unroll
        for (int m = 0; m < 32; m += 2) {
            const ull x0 = xa[m], x1 = xa[m + 1];
            a0 = ffma2(wA[m],     x0, a0);
            a1 = ffma2(wA[m + 1], x1, a1);
            a2 = ffma2(wB[m],     x0, a2);
            a3 = ffma2(wB[m + 1], x1, a3);
        }
        const float2 s0 = unpack2(fadd2(a0, a1));
        const float2 s1 = unpack2(fadd2(a2, a3));
        const ull r = pack2(bc0 + s0.x + s0.y, bc1 + s1.x + s1.y);

        const int n  = base + i;               // n = b*S + t
        const int bb = n >> 10, tt = n & 1023;
        g_xz[((size_t)tt * B_ + bb) * 128 + j] = r;
        buf ^= 1;
        // no second barrier: next iter writes the OTHER buffer
    }
}

// =====================================================================
// Kernel B: LSTM recurrence — uniform 1 CTA/SM, ONE barrier per step.
// 128 CTAs x 256 thr, 2 batch rows per CTA (8 warps = 2/SMSP uniform).
//   tid: r = tid>>7 (row), p = tid&127 (pair), u = p>>1, s = p&1.
//   s=0 computes (z_i, z_f); s=1 computes (z_c, z_o); exchange via
//   shfl_xor(1). Even lane does the cell update + 32-bit h store.
//   Warps 3 / 7 additionally compute the dense head for step t-1 of
//   rows 0 / 1 from the stable parity buffer, fully overlapped.
// =====================================================================
__global__ void __launch_bounds__(256, 1) lstm_recur(
    const float* __restrict__ rec, const float* __restrict__ dw,
    const float* __restrict__ db, float* __restrict__ out)
{
    const int tid  = threadIdx.x;
    const int p    = tid & 127;
    const int r    = tid >> 7;
    const int u    = p >> 1;
    const int s    = p & 1;
    const int lane = tid & 31;
    const int wid  = tid >> 5;
    const int brow = blockIdx.x * 2 + r;
    const int c0   = u + (s ? 128 : 0);
    const int c1   = c0 + 64;

    // recurrent weights packed along k, own two columns
    ull wA[32], wB[32];
#pragma unroll
    for (int m = 0; m < 32; m++) {
        wA[m] = pack2(rec[(2 * m) * G_ + c0], rec[(2 * m + 1) * G_ + c0]);
        wB[m] = pack2(rec[(2 * m) * G_ + c1], rec[(2 * m + 1) * G_ + c1]);
    }

    __shared__ __align__(16) ull hpk[2][2][32];   // [parity][row][m] = (h_2m, h_2m+1)

    if (tid < 64) hpk[1][tid >> 5][tid & 31] = 0ull;   // h(-1) = 0 at parity 1

    const bool isDense = (wid == 3) | (wid == 7);      // warp 3 -> row 0, warp 7 -> row 1
    const float dwa   = dw[2 * lane];
    const float dwb   = dw[2 * lane + 1];
    const float dbias = db[0];

    float c = 0.f;
    const size_t ZS = (size_t)B_ * 128;
    const ull* zp = g_xz + (size_t)brow * 128 + p;
    ull z0 = zp[0];                  // depth-2 z prefetch
    ull z1 = zp[ZS];
    zp += 2 * ZS;
    __syncthreads();

#pragma unroll 2
    for (int t = 0; t < S_; t++) {
        const int  pr = (t & 1) ^ 1;            // parity holding h(t-1)
        const ull* hp = hpk[pr][r];

        // dense head for t-1, overlapped with other warps' matvec
        if (isDense && t > 0) {
            const float2 hh = unpack2(hp[lane]);
            float pd = hh.x * dwa + hh.y * dwb;
#pragma unroll
            for (int off = 16; off; off >>= 1)
                pd += __shfl_xor_sync(0xffffffffu, pd, off);
            if (lane == 0)
                out[(size_t)brow * S_ + (t - 1)] = sigmoidf_acc(pd + dbias);
        }

        // matvec: 32 broadcast LDS + 64 FFMA2 in 4 chains
        ull a0 = 0, a1 = 0, a2 = 0, a3 = 0;
#pragma unroll
        for (int m = 0; m < 32; m += 2) {
            const ull h0 = hp[m], h1 = hp[m + 1];
            a0 = ffma2(wA[m],     h0, a0);
            a1 = ffma2(wA[m + 1], h1, a1);
            a2 = ffma2(wB[m],     h0, a2);
            a3 = ffma2(wB[m + 1], h1, a3);
        }
        const float2 sa  = unpack2(fadd2(a0, a1));
        const float2 sb  = unpack2(fadd2(a2, a3));
        const float2 zin = unpack2(z0);
        z0 = z1;
        if (t + 2 < S_) z1 = *zp;
        zp += ZS;
        const float zv0 = zin.x + sa.x + sa.y;  // z_i (s=0) / z_c (s=1)
        const float zv1 = zin.y + sb.x + sb.y;  // z_f (s=0) / z_o (s=1)

        // own activations, then in-warp exchange with partner lane
        const float g0 = s ? tanh_fast(zv0) : sig_fast(zv0);
        const float g1 = sig_fast(zv1);
        const float t0 = __shfl_xor_sync(0xffffffffu, g0, 1);
        const float t1 = __shfl_xor_sync(0xffffffffu, g1, 1);

        if (s == 0) {                           // lane holds (i,f); partner sent (tc,o)
            c = fmaf(g1, c, g0 * t0);
            const float h = t1 * tanh_fast(c);
            ((float*)hpk[t & 1][r])[u] = h;     // publish h_u(t)
        }
        __syncthreads();                        // the ONLY barrier per step
    }

    // final output: h(S-1) at parity 1
    if (isDense) {
        const float2 hh = unpack2(hpk[1][r][lane]);
        float pd = hh.x * dwa + hh.y * dwb;
#pragma unroll
        for (int off = 16; off; off >>= 1)
            pd += __shfl_xor_sync(0xffffffffu, pd, off);
        if (lane == 0)
            out[(size_t)brow * S_ + (S_ - 1)] = sigmoidf_acc(pd + dbias);
    }
}

// =====================================================================
extern "C" void kernel_launch(void* const* d_in, const int* in_sizes, int n_in,
                              void* d_out, int out_size)
{
    const float* x    = (const float*)d_in[0];  // [256,1024,64]
    const float* kern = (const float*)d_in[1];  // [64,256]
    const float* rec  = (const float*)d_in[2];  // [64,256]
    const float* bias = (const float*)d_in[3];  // [256]
    const float* dw   = (const float*)d_in[4];  // [64,1]
    const float* db   = (const float*)d_in[5];  // [1]
    float* out = (float*)d_out;                 // [256,1024,1]

    lstm_xgemm<<<2048, 128>>>(x, kern, bias);
    lstm_recur<<<128, 256>>>(rec, dw, db, out);
}

// round 6
// speedup vs baseline: 1.2286x; 1.2286x over previous
#include <cuda_runtime.h>

typedef unsigned long long ull;

// ---------------- packed f32x2 helpers (Blackwell FFMA2 path) ----------------
__device__ __forceinline__ ull pack2(float a, float b) {
    ull r; asm("mov.b64 %0, {%1,%2};" : "=l"(r) : "f"(a), "f"(b)); return r;
}
__device__ __forceinline__ float2 unpack2(ull v) {
    float2 f; asm("mov.b64 {%0,%1}, %2;" : "=f"(f.x), "=f"(f.y) : "l"(v)); return f;
}
__device__ __forceinline__ ull ffma2(ull a, ull b, ull c) {
    ull d; asm("fma.rn.f32x2 %0, %1, %2, %3;" : "=l"(d) : "l"(a), "l"(b), "l"(c)); return d;
}
__device__ __forceinline__ ull fadd2(ull a, ull b) {
    ull d; asm("add.rn.f32x2 %0, %1, %2;" : "=l"(d) : "l"(a), "l"(b)); return d;
}

// HW tanh (single MUFU op); validated rel_err ~7e-7 end-to-end
__device__ __forceinline__ float tanh_fast(float x) {
    float y; asm("tanh.approx.f32 %0, %1;" : "=f"(y) : "f"(x)); return y;
}
__device__ __forceinline__ float sig_fast(float x) {
    return fmaf(0.5f, tanh_fast(0.5f * x), 0.5f);
}
__device__ __forceinline__ float sigmoidf_acc(float x) {
    return __fdividef(1.f, 1.f + __expf(-x));
}

#define B_  256
#define S_  1024
#define F_  64
#define H_  64
#define G_  256   // 4*H

// Pair mapping: pair index p -> u = p>>1, s = p&1
//   s=0: columns (u,     u+64 ) = (z_i[u],  z_f[u])
//   s=1: columns (u+128, u+192) = (z_c[u],  z_o[u])
// xz scratch: [t][b][p] packed float2 (col c0, col c1). 268MB.
__device__ ull g_xz[(size_t)S_ * B_ * 128];

// =====================================================================
// Kernel A: xz = x @ kernel + bias
// 1024 CTAs x 256 thr; per iter one quad (4 global rows); 64 iters.
// 4-slot shared ring + depth-3 x prefetch so LDG latency never binds.
// =====================================================================
__global__ void __launch_bounds__(256, 1) lstm_xgemm(
    const float* __restrict__ x, const float* __restrict__ kern,
    const float* __restrict__ bias)
{
    const int tid  = threadIdx.x;
    const int j    = tid & 127;
    const int half = tid >> 7;
    const int u    = j >> 1;
    const int s    = j & 1;
    const int c0   = u + (s ? 128 : 0);
    const int c1   = c0 + 64;

    // weights packed along k: wX[m] = (kern[2m][c], kern[2m+1][c])
    ull wA[32], wB[32];
#pragma unroll
    for (int m = 0; m < 32; m++) {
        wA[m] = pack2(kern[(2 * m) * G_ + c0], kern[(2 * m + 1) * G_ + c0]);
        wB[m] = pack2(kern[(2 * m) * G_ + c1], kern[(2 * m + 1) * G_ + c1]);
    }
    const float bc0 = bias[c0], bc1 = bias[c1];

    __shared__ __align__(16) ull xpk[4][4][32];   // [slot][row][kpair] ring

    // loader threads: tid<128 -> row lr of the quad, k-pair lm
    const int lr = (tid >> 5) & 3;
    const int lm = tid & 31;
    const int qbase = blockIdx.x * 64;

    float2 v = make_float2(0.f, 0.f);
    if (tid < 128) {
        float2 t0 = *(const float2*)(x + (size_t)((qbase + 0) * 4 + lr) * F_ + 2 * lm);
        xpk[0][lr][lm] = pack2(t0.x, t0.y);
        float2 t1 = *(const float2*)(x + (size_t)((qbase + 1) * 4 + lr) * F_ + 2 * lm);
        xpk[1][lr][lm] = pack2(t1.x, t1.y);
        v = *(const float2*)(x + (size_t)((qbase + 2) * 4 + lr) * F_ + 2 * lm);
    }
    __syncthreads();

#pragma unroll 4
    for (int i = 0; i < 64; i++) {
        // loader: publish quad i+2 (loaded 1+ iters ago), start load of i+3
        if (tid < 128 && i + 2 < 64) {
            xpk[(i + 2) & 3][lr][lm] = pack2(v.x, v.y);
            if (i + 3 < 64)
                v = *(const float2*)(x + (size_t)((qbase + i + 3) * 4 + lr) * F_ + 2 * lm);
        }

        const ull* xa = xpk[i & 3][half];       // row n0
        const ull* xb = xpk[i & 3][half + 2];   // row n0+2
        ull a0 = 0, a1 = 0, a2 = 0, a3 = 0;     // row A, cols c0/c1
        ull b0 = 0, b1 = 0, b2 = 0, b3 = 0;     // row B
#pragma unroll
        for (int m = 0; m < 32; m += 2) {
            const ull xa0 = xa[m], xa1 = xa[m + 1];
            const ull xb0 = xb[m], xb1 = xb[m + 1];
            a0 = ffma2(wA[m],     xa0, a0);
            a1 = ffma2(wA[m + 1], xa1, a1);
            a2 = ffma2(wB[m],     xa0, a2);
            a3 = ffma2(wB[m + 1], xa1, a3);
            b0 = ffma2(wA[m],     xb0, b0);
            b1 = ffma2(wA[m + 1], xb1, b1);
            b2 = ffma2(wB[m],     xb0, b2);
            b3 = ffma2(wB[m + 1], xb1, b3);
        }
        const float2 sa0 = unpack2(fadd2(a0, a1));
        const float2 sa1 = unpack2(fadd2(a2, a3));
        const float2 sb0 = unpack2(fadd2(b0, b1));
        const float2 sb1 = unpack2(fadd2(b2, b3));
        const ull r0 = pack2(bc0 + sa0.x + sa0.y, bc1 + sa1.x + sa1.y);
        const ull r1 = pack2(bc0 + sb0.x + sb0.y, bc1 + sb1.x + sb1.y);

        const int n0 = (qbase + i) * 4 + half;   // global row = b*S + t
        const int n1 = n0 + 2;
        {
            const int bb = n0 >> 10, tt = n0 & 1023;
            g_xz[((size_t)tt * B_ + bb) * 128 + j] = r0;
        }
        {
            const int bb = n1 >> 10, tt = n1 & 1023;
            g_xz[((size_t)tt * B_ + bb) * 128 + j] = r1;
        }
        __syncthreads();
    }
}

// =====================================================================
// Kernel B: LSTM recurrence — uniform 1 CTA/SM, ONE barrier per step,
// and a DEPTH-8 register ring for the z stream (the round<=5 pin was
// z-load latency exposed through a depth-2 prefetch).
// 128 CTAs x 256 thr, 2 batch rows per CTA (8 warps = 2/SMSP uniform).
// =====================================================================
__global__ void __launch_bounds__(256, 1) lstm_recur(
    const float* __restrict__ rec, const float* __restrict__ dw,
    const float* __restrict__ db, float* __restrict__ out)
{
    const int tid  = threadIdx.x;
    const int p    = tid & 127;
    const int r    = tid >> 7;
    const int u    = p >> 1;
    const int s    = p & 1;
    const int lane = tid & 31;
    const int wid  = tid >> 5;
    const int brow = blockIdx.x * 2 + r;
    const int c0   = u + (s ? 128 : 0);
    const int c1   = c0 + 64;

    // recurrent weights packed along k, own two columns
    ull wA[32], wB[32];
#pragma unroll
    for (int m = 0; m < 32; m++) {
        wA[m] = pack2(rec[(2 * m) * G_ + c0], rec[(2 * m + 1) * G_ + c0]);
        wB[m] = pack2(rec[(2 * m) * G_ + c1], rec[(2 * m + 1) * G_ + c1]);
    }

    __shared__ __align__(16) ull hpk[2][2][32];   // [parity][row][m] = (h_2m, h_2m+1)

    if (tid < 64) hpk[1][tid >> 5][tid & 31] = 0ull;   // h(-1) = 0 at parity 1

    const bool isDense = (wid == 3) | (wid == 7);      // warp 3 -> row 0, warp 7 -> row 1
    const float dwa   = dw[2 * lane];
    const float dwb   = dw[2 * lane + 1];
    const float dbias = db[0];

    float c = 0.f;
    const size_t ZS = (size_t)B_ * 128;
    const ull* zp = g_xz + (size_t)brow * 128 + p;

    // ---- depth-8 z prefetch ring ----
    ull zr[8];
#pragma unroll
    for (int d = 0; d < 8; d++) zr[d] = zp[(size_t)d * ZS];
    zp += 8 * ZS;
    __syncthreads();

#pragma unroll 8
    for (int t = 0; t < S_; t++) {
        const int  pr = (t & 1) ^ 1;            // parity holding h(t-1)
        const ull* hp = hpk[pr][r];

        const ull zcur = zr[t & 7];             // z for this step (issued 8 steps ago)
        if (t + 8 < S_) zr[t & 7] = *zp;        // refill slot with step t+8
        zp += ZS;

        // dense head for t-1, overlapped with other warps' matvec
        if (isDense && t > 0) {
            const float2 hh = unpack2(hp[lane]);
            float pd = hh.x * dwa + hh.y * dwb;
#pragma unroll
            for (int off = 16; off; off >>= 1)
                pd += __shfl_xor_sync(0xffffffffu, pd, off);
            if (lane == 0)
                out[(size_t)brow * S_ + (t - 1)] = sigmoidf_acc(pd + dbias);
        }

        // matvec: 32 broadcast LDS + 64 FFMA2 in 4 chains
        ull a0 = 0, a1 = 0, a2 = 0, a3 = 0;
#pragma unroll
        for (int m = 0; m < 32; m += 2) {
            const ull h0 = hp[m], h1 = hp[m + 1];
            a0 = ffma2(wA[m],     h0, a0);
            a1 = ffma2(wA[m + 1], h1, a1);
            a2 = ffma2(wB[m],     h0, a2);
            a3 = ffma2(wB[m + 1], h1, a3);
        }
        const float2 sa  = unpack2(fadd2(a0, a1));
        const float2 sb  = unpack2(fadd2(a2, a3));
        const float2 zin = unpack2(zcur);
        const float zv0 = zin.x + sa.x + sa.y;  // z_i (s=0) / z_c (s=1)
        const float zv1 = zin.y + sb.x + sb.y;  // z_f (s=0) / z_o (s=1)

        // own activations, then in-warp exchange with partner lane
        const float g0 = s ? tanh_fast(zv0) : sig_fast(zv0);
        const float g1 = sig_fast(zv1);
        const float t0 = __shfl_xor_sync(0xffffffffu, g0, 1);
        const float t1 = __shfl_xor_sync(0xffffffffu, g1, 1);

        if (s == 0) {                           // lane holds (i,f); partner sent (tc,o)
            c = fmaf(g1, c, g0 * t0);
            const float h = t1 * tanh_fast(c);
            ((float*)hpk[t & 1][r])[u] = h;     // publish h_u(t)
        }
        __syncthreads();                        // the ONLY barrier per step
    }

    // final output: h(S-1) at parity 1
    if (isDense) {
        const float2 hh = unpack2(hpk[1][r][lane]);
        float pd = hh.x * dwa + hh.y * dwb;
#pragma unroll
        for (int off = 16; off; off >>= 1)
            pd += __shfl_xor_sync(0xffffffffu, pd, off);
        if (lane == 0)
            out[(size_t)brow * S_ + (S_ - 1)] = sigmoidf_acc(pd + dbias);
    }
}

// =====================================================================
extern "C" void kernel_launch(void* const* d_in, const int* in_sizes, int n_in,
                              void* d_out, int out_size)
{
    const float* x    = (const float*)d_in[0];  // [256,1024,64]
    const float* kern = (const float*)d_in[1];  // [64,256]
    const float* rec  = (const float*)d_in[2];  // [64,256]
    const float* bias = (const float*)d_in[3];  // [256]
    const float* dw   = (const float*)d_in[4];  // [64,1]
    const float* db   = (const float*)d_in[5];  // [1]
    float* out = (float*)d_out;                 // [256,1024,1]

    lstm_xgemm<<<1024, 256>>>(x, kern, bias);
    lstm_recur<<<128, 256>>>(rec, dw, db, out);
}

// round 7
// speedup vs baseline: 1.4996x; 1.2206x over previous
#include <cuda_runtime.h>

typedef unsigned long long ull;

// ---------------- packed f32x2 helpers (Blackwell FFMA2 path) ----------------
__device__ __forceinline__ ull pack2(float a, float b) {
    ull r; asm("mov.b64 %0, {%1,%2};" : "=l"(r) : "f"(a), "f"(b)); return r;
}
__device__ __forceinline__ float2 unpack2(ull v) {
    float2 f; asm("mov.b64 {%0,%1}, %2;" : "=f"(f.x), "=f"(f.y) : "l"(v)); return f;
}
__device__ __forceinline__ ull ffma2(ull a, ull b, ull c) {
    ull d; asm("fma.rn.f32x2 %0, %1, %2, %3;" : "=l"(d) : "l"(a), "l"(b), "l"(c)); return d;
}
__device__ __forceinline__ ull fadd2(ull a, ull b) {
    ull d; asm("add.rn.f32x2 %0, %1, %2;" : "=l"(d) : "l"(a), "l"(b)); return d;
}

// HW tanh (single MUFU op); validated rel_err ~7e-7 end-to-end
__device__ __forceinline__ float tanh_fast(float x) {
    float y; asm("tanh.approx.f32 %0, %1;" : "=f"(y) : "f"(x)); return y;
}
__device__ __forceinline__ float sig_fast(float x) {
    return fmaf(0.5f, tanh_fast(0.5f * x), 0.5f);
}
__device__ __forceinline__ float sigmoidf_acc(float x) {
    return __fdividef(1.f, 1.f + __expf(-x));
}

#define B_  256
#define S_  1024
#define F_  64
#define H_  64
#define G_  256   // 4*H

// Pair mapping: pair index p -> u = p>>1, s = p&1
//   s=0: columns (u,     u+64 ) = (z_i[u],  z_f[u])
//   s=1: columns (u+128, u+192) = (z_c[u],  z_o[u])
// xz scratch: [t][b][p] packed float2 (col c0, col c1). 268MB.
__device__ ull   g_xz[(size_t)S_ * B_ * 128];
// h scratch: [b][t][u] floats. 64MB.
__device__ float g_h[(size_t)B_ * S_ * H_];

// =====================================================================
// Kernel A: xz = x @ kernel + bias   (round-6 version, unchanged)
// =====================================================================
__global__ void __launch_bounds__(256, 1) lstm_xgemm(
    const float* __restrict__ x, const float* __restrict__ kern,
    const float* __restrict__ bias)
{
    const int tid  = threadIdx.x;
    const int j    = tid & 127;
    const int half = tid >> 7;
    const int u    = j >> 1;
    const int s    = j & 1;
    const int c0   = u + (s ? 128 : 0);
    const int c1   = c0 + 64;

    ull wA[32], wB[32];
#pragma unroll
    for (int m = 0; m < 32; m++) {
        wA[m] = pack2(kern[(2 * m) * G_ + c0], kern[(2 * m + 1) * G_ + c0]);
        wB[m] = pack2(kern[(2 * m) * G_ + c1], kern[(2 * m + 1) * G_ + c1]);
    }
    const float bc0 = bias[c0], bc1 = bias[c1];

    __shared__ __align__(16) ull xpk[4][4][32];   // [slot][row][kpair] ring

    const int lr = (tid >> 5) & 3;
    const int lm = tid & 31;
    const int qbase = blockIdx.x * 64;

    float2 v = make_float2(0.f, 0.f);
    if (tid < 128) {
        float2 t0 = *(const float2*)(x + (size_t)((qbase + 0) * 4 + lr) * F_ + 2 * lm);
        xpk[0][lr][lm] = pack2(t0.x, t0.y);
        float2 t1 = *(const float2*)(x + (size_t)((qbase + 1) * 4 + lr) * F_ + 2 * lm);
        xpk[1][lr][lm] = pack2(t1.x, t1.y);
        v = *(const float2*)(x + (size_t)((qbase + 2) * 4 + lr) * F_ + 2 * lm);
    }
    __syncthreads();

#pragma unroll 4
    for (int i = 0; i < 64; i++) {
        if (tid < 128 && i + 2 < 64) {
            xpk[(i + 2) & 3][lr][lm] = pack2(v.x, v.y);
            if (i + 3 < 64)
                v = *(const float2*)(x + (size_t)((qbase + i + 3) * 4 + lr) * F_ + 2 * lm);
        }

        const ull* xa = xpk[i & 3][half];
        const ull* xb = xpk[i & 3][half + 2];
        ull a0 = 0, a1 = 0, a2 = 0, a3 = 0;
        ull b0 = 0, b1 = 0, b2 = 0, b3 = 0;
#pragma unroll
        for (int m = 0; m < 32; m += 2) {
            const ull xa0 = xa[m], xa1 = xa[m + 1];
            const ull xb0 = xb[m], xb1 = xb[m + 1];
            a0 = ffma2(wA[m],     xa0, a0);
            a1 = ffma2(wA[m + 1], xa1, a1);
            a2 = ffma2(wB[m],     xa0, a2);
            a3 = ffma2(wB[m + 1], xa1, a3);
            b0 = ffma2(wA[m],     xb0, b0);
            b1 = ffma2(wA[m + 1], xb1, b1);
            b2 = ffma2(wB[m],     xb0, b2);
            b3 = ffma2(wB[m + 1], xb1, b3);
        }
        const float2 sa0 = unpack2(fadd2(a0, a1));
        const float2 sa1 = unpack2(fadd2(a2, a3));
        const float2 sb0 = unpack2(fadd2(b0, b1));
        const float2 sb1 = unpack2(fadd2(b2, b3));
        const ull r0 = pack2(bc0 + sa0.x + sa0.y, bc1 + sa1.x + sa1.y);
        const ull r1 = pack2(bc0 + sb0.x + sb0.y, bc1 + sb1.x + sb1.y);

        const int n0 = (qbase + i) * 4 + half;
        const int n1 = n0 + 2;
        {
            const int bb = n0 >> 10, tt = n0 & 1023;
            g_xz[((size_t)tt * B_ + bb) * 128 + j] = r0;
        }
        {
            const int bb = n1 >> 10, tt = n1 & 1023;
            g_xz[((size_t)tt * B_ + bb) * 128 + j] = r1;
        }
        __syncthreads();
    }
}

// =====================================================================
// Kernel B: LSTM recurrence. No dense head (moved to kernel C); all 8
// warps uniform. Named barrier per row decouples the 2 batch rows.
// 128 CTAs x 256 thr, depth-8 z register ring, 8 FFMA2 accumulators.
// h(t) streamed to g_h for the head kernel.
// =====================================================================
__global__ void __launch_bounds__(256, 1) lstm_recur(
    const float* __restrict__ rec)
{
    const int tid  = threadIdx.x;
    const int p    = tid & 127;
    const int r    = tid >> 7;
    const int u    = p >> 1;
    const int s    = p & 1;
    const int brow = blockIdx.x * 2 + r;
    const int c0   = u + (s ? 128 : 0);
    const int c1   = c0 + 64;

    // recurrent weights packed along k, own two columns
    ull wA[32], wB[32];
#pragma unroll
    for (int m = 0; m < 32; m++) {
        wA[m] = pack2(rec[(2 * m) * G_ + c0], rec[(2 * m + 1) * G_ + c0]);
        wB[m] = pack2(rec[(2 * m) * G_ + c1], rec[(2 * m + 1) * G_ + c1]);
    }

    __shared__ __align__(16) ull hpk[2][2][32];   // [parity][row][m] = (h_2m, h_2m+1)

    if (tid < 64) hpk[1][tid >> 5][tid & 31] = 0ull;   // h(-1) = 0 at parity 1

    float c = 0.f;
    const size_t ZS = (size_t)B_ * 128;
    const ull* zp = g_xz + (size_t)brow * 128 + p;
    float* hout = g_h + (size_t)brow * S_ * H_ + u;    // [t][u] stream

    // depth-8 z prefetch ring
    ull zr[8];
#pragma unroll
    for (int d = 0; d < 8; d++) zr[d] = zp[(size_t)d * ZS];
    zp += 8 * ZS;
    __syncthreads();

    const int barid = r + 1;     // named barrier per row (128 threads each)

#pragma unroll 8
    for (int t = 0; t < S_; t++) {
        const int  pr = (t & 1) ^ 1;            // parity holding h(t-1)
        const ull* hp = hpk[pr][r];

        const ull zcur = zr[t & 7];             // z issued 8 steps ago
        if (t + 8 < S_) zr[t & 7] = *zp;
        zp += ZS;

        // matvec: 32 broadcast LDS + 64 FFMA2, 8 chains of 8
        ull a0 = 0, a1 = 0, a2 = 0, a3 = 0;
        ull b0 = 0, b1 = 0, b2 = 0, b3 = 0;
#pragma unroll
        for (int m = 0; m < 32; m += 4) {
            const ull h0 = hp[m],     h1 = hp[m + 1];
            const ull h2 = hp[m + 2], h3 = hp[m + 3];
            a0 = ffma2(wA[m],     h0, a0);
            a1 = ffma2(wA[m + 1], h1, a1);
            a2 = ffma2(wB[m],     h0, a2);
            a3 = ffma2(wB[m + 1], h1, a3);
            b0 = ffma2(wA[m + 2], h2, b0);
            b1 = ffma2(wA[m + 3], h3, b1);
            b2 = ffma2(wB[m + 2], h2, b2);
            b3 = ffma2(wB[m + 3], h3, b3);
        }
        const float2 sa  = unpack2(fadd2(fadd2(a0, a1), fadd2(b0, b1)));
        const float2 sb  = unpack2(fadd2(fadd2(a2, a3), fadd2(b2, b3)));
        const float2 zin = unpack2(zcur);
        const float zv0 = zin.x + sa.x + sa.y;  // z_i (s=0) / z_c (s=1)
        const float zv1 = zin.y + sb.x + sb.y;  // z_f (s=0) / z_o (s=1)

        // own activations, then in-warp exchange with partner lane
        const float g0 = s ? tanh_fast(zv0) : sig_fast(zv0);
        const float g1 = sig_fast(zv1);
        const float t0 = __shfl_xor_sync(0xffffffffu, g0, 1);
        const float t1 = __shfl_xor_sync(0xffffffffu, g1, 1);

        if (s == 0) {                           // lane holds (i,f); partner sent (tc,o)
            c = fmaf(g1, c, g0 * t0);
            const float h = t1 * tanh_fast(c);
            ((float*)hpk[t & 1][r])[u] = h;     // publish h_u(t) for next step
            hout[(size_t)t * H_] = h;           // stream to gmem (off-chain STG)
        }
        asm volatile("bar.sync %0, 128;" :: "r"(barid) : "memory");
    }
}

// =====================================================================
// Kernel C: dense head  out[b,t] = sigmoid(h[b,t,:]·dw + db)
// One warp per output: lane l loads (h[2l], h[2l+1]) coalesced,
// 5-level shfl reduce, accurate sigmoid. 32768 CTAs x 256 thr.
// =====================================================================
__global__ void __launch_bounds__(256, 4) lstm_head(
    const float* __restrict__ dw, const float* __restrict__ db,
    float* __restrict__ out)
{
    const int lane = threadIdx.x & 31;
    const int o    = blockIdx.x * 8 + (threadIdx.x >> 5);   // output index b*S+t

    const float2 hv = *(const float2*)(g_h + (size_t)o * H_ + 2 * lane);
    const float2 wv = *(const float2*)(dw + 2 * lane);
    float pd = hv.x * wv.x + hv.y * wv.y;
#pragma unroll
    for (int off = 16; off; off >>= 1)
        pd += __shfl_xor_sync(0xffffffffu, pd, off);
    if (lane == 0)
        out[o] = sigmoidf_acc(pd + db[0]);
}

// =====================================================================
extern "C" void kernel_launch(void* const* d_in, const int* in_sizes, int n_in,
                              void* d_out, int out_size)
{
    const float* x    = (const float*)d_in[0];  // [256,1024,64]
    const float* kern = (const float*)d_in[1];  // [64,256]
    const float* rec  = (const float*)d_in[2];  // [64,256]
    const float* bias = (const float*)d_in[3];  // [256]
    const float* dw   = (const float*)d_in[4];  // [64,1]
    const float* db   = (const float*)d_in[5];  // [1]
    float* out = (float*)d_out;                 // [256,1024,1]

    lstm_xgemm<<<1024, 256>>>(x, kern, bias);
    lstm_recur<<<128, 256>>>(rec);
    lstm_head<<<(B_ * S_) / 8, 256>>>(dw, db, out);
}